// round 2
// baseline (speedup 1.0000x reference)
#include <cuda_runtime.h>

#define D       256
#define KCODES  1024
#define BM      128
#define BN      64
#define BD      32
#define TM      8
#define TN      4
#define NTHREADS 256

__device__ float g_c_sq[KCODES];

// One warp per codebook row: c_sq[k] = sum_d codebook[k][d]^2
__global__ void csq_kernel(const float* __restrict__ cb) {
    int warp = (blockIdx.x * blockDim.x + threadIdx.x) >> 5;
    int lane = threadIdx.x & 31;
    if (warp >= KCODES) return;
    const float* row = cb + (size_t)warp * D;
    float s = 0.f;
    #pragma unroll
    for (int d = lane; d < D; d += 32) { float v = row[d]; s += v * v; }
    #pragma unroll
    for (int o = 16; o; o >>= 1) s += __shfl_xor_sync(0xffffffffu, s, o);
    if (lane == 0) g_c_sq[warp] = s;
}

// Fused distance-GEMM + argmin + gather.
// Block: 128 tokens x all 1024 codes (16 tiles of 64). Microtile 8x4 per thread.
__global__ __launch_bounds__(NTHREADS, 2)
void vq_kernel(const float* __restrict__ z, const float* __restrict__ cb,
               float* __restrict__ zq, float* __restrict__ idx_out) {
    __shared__ float zs[BD][BM + 1];   // +1 pad: conflict-free
    __shared__ float cs[BD][BN + 1];
    __shared__ float s_csq[BN];
    __shared__ int   s_idx[BM];

    const int tid = threadIdx.x;
    const int m0  = blockIdx.x * BM;
    const int ty  = tid >> 4;          // 0..15 -> token group
    const int tx  = tid & 15;          // 0..15 -> code group
    const int mrow = ty * TM;
    const int ncol = tx * TN;

    float best[TM];
    int   bidx[TM];
    #pragma unroll
    for (int i = 0; i < TM; i++) { best[i] = 3.402823466e38f; bidx[i] = 0; }

    for (int n0 = 0; n0 < KCODES; n0 += BN) {
        float acc[TM][TN];
        #pragma unroll
        for (int i = 0; i < TM; i++)
            #pragma unroll
            for (int j = 0; j < TN; j++) acc[i][j] = 0.f;

        if (tid < BN) s_csq[tid] = g_c_sq[n0 + tid];

        for (int d0 = 0; d0 < D; d0 += BD) {
            // Load z tile [BM x BD] -> zs[d][m]   (coalesced: lane = d)
            #pragma unroll
            for (int i = 0; i < (BM * BD) / NTHREADS; i++) {
                int lin = tid + i * NTHREADS;
                int m = lin >> 5, d = lin & 31;
                zs[d][m] = z[(size_t)(m0 + m) * D + d0 + d];
            }
            // Load codebook tile [BN x BD] -> cs[d][n]
            #pragma unroll
            for (int i = 0; i < (BN * BD) / NTHREADS; i++) {
                int lin = tid + i * NTHREADS;
                int n = lin >> 5, d = lin & 31;
                cs[d][n] = cb[(size_t)(n0 + n) * D + d0 + d];
            }
            __syncthreads();

            #pragma unroll
            for (int d = 0; d < BD; d++) {
                float zf[TM], cf[TN];
                #pragma unroll
                for (int i = 0; i < TM; i++) zf[i] = zs[d][mrow + i];
                #pragma unroll
                for (int j = 0; j < TN; j++) cf[j] = cs[d][ncol + j];
                #pragma unroll
                for (int i = 0; i < TM; i++)
                    #pragma unroll
                    for (int j = 0; j < TN; j++)
                        acc[i][j] += zf[i] * cf[j];
            }
            __syncthreads();
        }

        // dist = c_sq - 2*dot (z_sq constant per token: same argmin).
        // Ascending j + strict '<' -> lowest index wins ties, matching argmin.
        #pragma unroll
        for (int j = 0; j < TN; j++) {
            float csq = s_csq[ncol + j];
            int   gidx = n0 + ncol + j;
            #pragma unroll
            for (int i = 0; i < TM; i++) {
                float dist = fmaf(-2.0f, acc[i][j], csq);
                if (dist < best[i]) { best[i] = dist; bidx[i] = gidx; }
            }
        }
        __syncthreads();   // protect s_csq before next tile's write
    }

    // Reduce across the 16 tx-lanes (half-warp, width 16), lower index wins ties.
    #pragma unroll
    for (int i = 0; i < TM; i++) {
        float b = best[i]; int ix = bidx[i];
        #pragma unroll
        for (int o = 8; o; o >>= 1) {
            float ob = __shfl_xor_sync(0xffffffffu, b, o, 16);
            int   oi = __shfl_xor_sync(0xffffffffu, ix, o, 16);
            if (ob < b || (ob == b && oi < ix)) { b = ob; ix = oi; }
        }
        if (tx == 0) s_idx[mrow + i] = ix;
    }
    __syncthreads();

    // Write indices (as float: exactly representable 0..1023).
    if (tid < BM) idx_out[m0 + tid] = (float)s_idx[tid];

    // Gather z_q rows from codebook (L2-resident), vectorized float4.
    const float4* cb4 = reinterpret_cast<const float4*>(cb);
    float4* zq4 = reinterpret_cast<float4*>(zq);
    #pragma unroll 4
    for (int t = tid; t < BM * (D / 4); t += NTHREADS) {
        int m  = t >> 6;        // / (D/4)
        int c4 = t & 63;
        int code = s_idx[m];
        zq4[(size_t)(m0 + m) * (D / 4) + c4] = cb4[(size_t)code * (D / 4) + c4];
    }
}

extern "C" void kernel_launch(void* const* d_in, const int* in_sizes, int n_in,
                              void* d_out, int out_size) {
    const float* z  = (const float*)d_in[0];
    const float* cb = (const float*)d_in[1];
    const int M = in_sizes[0] / D;        // 32768 tokens
    float* out    = (float*)d_out;
    float* zq     = out;                  // [M, D]
    float* idxout = out + (size_t)M * D;  // [M] as float

    csq_kernel<<<(KCODES * 32 + NTHREADS - 1) / NTHREADS, NTHREADS>>>(cb);
    vq_kernel<<<M / BM, NTHREADS>>>(z, cb, zq, idxout);
}

// round 3
// speedup vs baseline: 1.1469x; 1.1469x over previous
#include <cuda_runtime.h>

#define D       256
#define KCODES  1024
#define BM      128
#define BN      64
#define BD      32
#define TM      8          // tokens per thread (4 packed pairs)
#define TMH     4
#define TN      4          // codes per thread
#define NTHREADS 256

__device__ float g_c_sq[KCODES];

typedef unsigned long long u64;

__device__ __forceinline__ u64 pack2(float x) {
    u64 r;
    asm("mov.b64 %0, {%1, %1};" : "=l"(r) : "f"(x));
    return r;
}
__device__ __forceinline__ void fma2(u64& d, u64 a, u64 b) {
    // d.lo += a.lo*b.lo ; d.hi += a.hi*b.hi   (IEEE fp32 per lane)
    asm("fma.rn.f32x2 %0, %1, %2, %0;" : "+l"(d) : "l"(a), "l"(b));
}
__device__ __forceinline__ void unpack2(u64 v, float& lo, float& hi) {
    asm("mov.b64 {%0, %1}, %2;" : "=f"(lo), "=f"(hi) : "l"(v));
}

// One warp per codebook row: c_sq[k] = sum_d codebook[k][d]^2
__global__ void csq_kernel(const float* __restrict__ cb) {
    int warp = (blockIdx.x * blockDim.x + threadIdx.x) >> 5;
    int lane = threadIdx.x & 31;
    if (warp >= KCODES) return;
    const float* row = cb + (size_t)warp * D;
    float s = 0.f;
    #pragma unroll
    for (int d = lane; d < D; d += 32) { float v = row[d]; s += v * v; }
    #pragma unroll
    for (int o = 16; o; o >>= 1) s += __shfl_xor_sync(0xffffffffu, s, o);
    if (lane == 0) g_c_sq[warp] = s;
}

// Fused distance-GEMM (packed f32x2 FMA) + argmin + gather.
__global__ __launch_bounds__(NTHREADS, 2)
void vq_kernel(const float* __restrict__ z, const float* __restrict__ cb,
               float* __restrict__ zq, float* __restrict__ idx_out) {
    // +2 pad keeps 8-byte alignment of every row (needed for LDS.64 on token pairs)
    __shared__ __align__(16) float zs[BD][BM + 2];
    __shared__ __align__(16) float cs[BD][BN + 2];
    __shared__ float s_csq[BN];
    __shared__ int   s_idx[BM];

    const int tid = threadIdx.x;
    const int m0  = blockIdx.x * BM;
    const int ty  = tid >> 4;          // 0..15 -> token group
    const int tx  = tid & 15;          // 0..15 -> code group
    const int mrow = ty * TM;
    const int ncol = tx * TN;

    float best[TM];
    int   bidx[TM];
    #pragma unroll
    for (int i = 0; i < TM; i++) { best[i] = 3.402823466e38f; bidx[i] = 0; }

    for (int n0 = 0; n0 < KCODES; n0 += BN) {
        u64 acc[TMH][TN];                     // packed pairs over adjacent tokens
        #pragma unroll
        for (int p = 0; p < TMH; p++)
            #pragma unroll
            for (int j = 0; j < TN; j++) acc[p][j] = 0ull;

        if (tid < BN) s_csq[tid] = g_c_sq[n0 + tid];

        for (int d0 = 0; d0 < D; d0 += BD) {
            // z tile [BM x BD] -> zs[d][m], float4 global loads
            #pragma unroll
            for (int i = 0; i < (BM * BD) / (4 * NTHREADS); i++) {
                int lin = tid + i * NTHREADS;
                int m = lin >> 3, dq = (lin & 7) << 2;
                float4 v = *reinterpret_cast<const float4*>(
                    z + (size_t)(m0 + m) * D + d0 + dq);
                zs[dq + 0][m] = v.x; zs[dq + 1][m] = v.y;
                zs[dq + 2][m] = v.z; zs[dq + 3][m] = v.w;
            }
            // codebook tile [BN x BD] -> cs[d][n]
            #pragma unroll
            for (int i = 0; i < (BN * BD) / (4 * NTHREADS); i++) {
                int lin = tid + i * NTHREADS;
                int n = lin >> 3, dq = (lin & 7) << 2;
                float4 v = *reinterpret_cast<const float4*>(
                    cb + (size_t)(n0 + n) * D + d0 + dq);
                cs[dq + 0][n] = v.x; cs[dq + 1][n] = v.y;
                cs[dq + 2][n] = v.z; cs[dq + 3][n] = v.w;
            }
            __syncthreads();

            #pragma unroll
            for (int d = 0; d < BD; d++) {
                u64 zp[TMH], cp[TN];
                #pragma unroll
                for (int p = 0; p < TMH; p++)
                    zp[p] = *reinterpret_cast<const u64*>(&zs[d][mrow + 2 * p]);
                #pragma unroll
                for (int j = 0; j < TN; j++)
                    cp[j] = pack2(cs[d][ncol + j]);
                #pragma unroll
                for (int p = 0; p < TMH; p++)
                    #pragma unroll
                    for (int j = 0; j < TN; j++)
                        fma2(acc[p][j], zp[p], cp[j]);
            }
            __syncthreads();
        }

        // dist = c_sq - 2*dot (z_sq is per-token constant: same argmin).
        // Ascending j + strict '<' -> lowest index wins ties, matching argmin.
        #pragma unroll
        for (int j = 0; j < TN; j++) {
            float csq = s_csq[ncol + j];
            int   gidx = n0 + ncol + j;
            #pragma unroll
            for (int p = 0; p < TMH; p++) {
                float dlo, dhi;
                unpack2(acc[p][j], dlo, dhi);
                float d0v = fmaf(-2.0f, dlo, csq);
                float d1v = fmaf(-2.0f, dhi, csq);
                if (d0v < best[2 * p + 0]) { best[2 * p + 0] = d0v; bidx[2 * p + 0] = gidx; }
                if (d1v < best[2 * p + 1]) { best[2 * p + 1] = d1v; bidx[2 * p + 1] = gidx; }
            }
        }
        __syncthreads();   // protect s_csq before next tile's write
    }

    // Reduce across the 16 tx-lanes (width 16), lower index wins ties.
    #pragma unroll
    for (int i = 0; i < TM; i++) {
        float b = best[i]; int ix = bidx[i];
        #pragma unroll
        for (int o = 8; o; o >>= 1) {
            float ob = __shfl_xor_sync(0xffffffffu, b, o, 16);
            int   oi = __shfl_xor_sync(0xffffffffu, ix, o, 16);
            if (ob < b || (ob == b && oi < ix)) { b = ob; ix = oi; }
        }
        if (tx == 0) s_idx[mrow + i] = ix;
    }
    __syncthreads();

    // Indices as float (0..1023: exactly representable).
    if (tid < BM) idx_out[m0 + tid] = (float)s_idx[tid];

    // Gather z_q rows from codebook (L2-resident), float4.
    const float4* cb4 = reinterpret_cast<const float4*>(cb);
    float4* zq4 = reinterpret_cast<float4*>(zq);
    #pragma unroll 4
    for (int t = tid; t < BM * (D / 4); t += NTHREADS) {
        int m  = t >> 6;        // / (D/4)
        int c4 = t & 63;
        int code = s_idx[m];
        zq4[(size_t)(m0 + m) * (D / 4) + c4] = cb4[(size_t)code * (D / 4) + c4];
    }
}

extern "C" void kernel_launch(void* const* d_in, const int* in_sizes, int n_in,
                              void* d_out, int out_size) {
    const float* z  = (const float*)d_in[0];
    const float* cb = (const float*)d_in[1];
    const int M = in_sizes[0] / D;        // 32768 tokens
    float* out    = (float*)d_out;
    float* zq     = out;                  // [M, D]
    float* idxout = out + (size_t)M * D;  // [M] as float

    csq_kernel<<<(KCODES * 32 + NTHREADS - 1) / NTHREADS, NTHREADS>>>(cb);
    vq_kernel<<<M / BM, NTHREADS>>>(z, cb, zq, idxout);
}

// round 6
// speedup vs baseline: 1.2448x; 1.0853x over previous
#include <cuda_runtime.h>

#define D       256
#define KCODES  1024
#define BM      128
#define BN      64
#define BD      32
#define TM      8          // tokens per thread (4 packed pairs)
#define TMH     4
#define TN      4          // codes per thread
#define NTHREADS 256

__device__ float g_c_sq[KCODES];

typedef unsigned long long u64;

__device__ __forceinline__ u64 pack2(float x) {
    u64 r;
    asm("mov.b64 %0, {%1, %1};" : "=l"(r) : "f"(x));
    return r;
}
__device__ __forceinline__ void fma2(u64& d, u64 a, u64 b) {
    // d.lo += a.lo*b.lo ; d.hi += a.hi*b.hi   (IEEE fp32 per lane)
    asm("fma.rn.f32x2 %0, %1, %2, %0;" : "+l"(d) : "l"(a), "l"(b));
}
__device__ __forceinline__ void unpack2(u64 v, float& lo, float& hi) {
    asm("mov.b64 {%0, %1}, %2;" : "=f"(lo), "=f"(hi) : "l"(v));
}

// One warp per codebook row: c_sq[k] = sum_d codebook[k][d]^2
__global__ void csq_kernel(const float* __restrict__ cb) {
    int warp = (blockIdx.x * blockDim.x + threadIdx.x) >> 5;
    int lane = threadIdx.x & 31;
    if (warp >= KCODES) return;
    const float* row = cb + (size_t)warp * D;
    float s = 0.f;
    #pragma unroll
    for (int d = lane; d < D; d += 32) { float v = row[d]; s += v * v; }
    #pragma unroll
    for (int o = 16; o; o >>= 1) s += __shfl_xor_sync(0xffffffffu, s, o);
    if (lane == 0) g_c_sq[warp] = s;
}

// Fused distance-GEMM (packed f32x2 FMA) + argmin + gather.
// XOR swizzle col = idx ^ (d & 28): conflict-free transpose STS, aligned
// LDS.128 reads, identical mapping at store and load time.
__global__ __launch_bounds__(NTHREADS, 2)
void vq_kernel(const float* __restrict__ z, const float* __restrict__ cb,
               float* __restrict__ zq, float* __restrict__ idx_out) {
    __shared__ __align__(16) float zs[BD][BM];   // rows 512B: 16B-aligned
    __shared__ __align__(16) float cs[BD][BN];   // rows 256B
    __shared__ float s_csq[BN];
    __shared__ int   s_idx[BM];

    const int tid = threadIdx.x;
    const int m0  = blockIdx.x * BM;
    const int ty  = tid >> 4;          // 0..15 -> token group
    const int tx  = tid & 15;          // 0..15 -> code group
    const int mrow = ty * TM;
    const int ncol = tx * TN;

    float best[TM];
    int   bidx[TM];
    #pragma unroll
    for (int i = 0; i < TM; i++) { best[i] = 3.402823466e38f; bidx[i] = 0; }

    for (int n0 = 0; n0 < KCODES; n0 += BN) {
        u64 acc[TMH][TN];                     // packed pairs over adjacent tokens
        #pragma unroll
        for (int p = 0; p < TMH; p++)
            #pragma unroll
            for (int j = 0; j < TN; j++) acc[p][j] = 0ull;

        if (tid < BN) s_csq[tid] = g_c_sq[n0 + tid];

        for (int d0 = 0; d0 < D; d0 += BD) {
            // z tile [BM x BD] -> zs[d][m ^ (d&28)], float4 global loads.
            // STS banks = (m mod 32) ^ dq with disjoint bit ranges: conflict-free.
            #pragma unroll
            for (int i = 0; i < (BM * BD) / (4 * NTHREADS); i++) {
                int lin = tid + i * NTHREADS;
                int m = lin >> 3, dq = (lin & 7) << 2;   // dq == (d & 28) for these rows
                float4 v = *reinterpret_cast<const float4*>(
                    z + (size_t)(m0 + m) * D + d0 + dq);
                int c = m ^ dq;
                zs[dq + 0][c] = v.x; zs[dq + 1][c] = v.y;
                zs[dq + 2][c] = v.z; zs[dq + 3][c] = v.w;
            }
            // codebook tile [BN x BD] -> cs[d][n ^ (d&28)]
            #pragma unroll
            for (int i = 0; i < (BN * BD) / (4 * NTHREADS); i++) {
                int lin = tid + i * NTHREADS;
                int n = lin >> 3, dq = (lin & 7) << 2;
                float4 v = *reinterpret_cast<const float4*>(
                    cb + (size_t)(n0 + n) * D + d0 + dq);
                int c = n ^ dq;
                cs[dq + 0][c] = v.x; cs[dq + 1][c] = v.y;
                cs[dq + 2][c] = v.z; cs[dq + 3][c] = v.w;
            }
            __syncthreads();

            #pragma unroll
            for (int d = 0; d < BD; d++) {
                const int X = d & 28;
                ulonglong2 za = *reinterpret_cast<const ulonglong2*>(&zs[d][mrow ^ X]);
                ulonglong2 zb = *reinterpret_cast<const ulonglong2*>(&zs[d][(mrow + 4) ^ X]);
                float4     cv = *reinterpret_cast<const float4*>(&cs[d][ncol ^ X]);
                u64 zp0 = za.x, zp1 = za.y, zp2 = zb.x, zp3 = zb.y;
                u64 cp[TN];
                cp[0] = pack2(cv.x); cp[1] = pack2(cv.y);
                cp[2] = pack2(cv.z); cp[3] = pack2(cv.w);
                #pragma unroll
                for (int j = 0; j < TN; j++) {
                    fma2(acc[0][j], zp0, cp[j]);
                    fma2(acc[1][j], zp1, cp[j]);
                    fma2(acc[2][j], zp2, cp[j]);
                    fma2(acc[3][j], zp3, cp[j]);
                }
            }
            __syncthreads();
        }

        // dist = c_sq - 2*dot (z_sq is per-token constant: same argmin).
        // Ascending j + strict '<' -> lowest index wins ties, matching argmin.
        #pragma unroll
        for (int j = 0; j < TN; j++) {
            float csq = s_csq[ncol + j];
            int   gidx = n0 + ncol + j;
            #pragma unroll
            for (int p = 0; p < TMH; p++) {
                float dlo, dhi;
                unpack2(acc[p][j], dlo, dhi);
                float d0v = fmaf(-2.0f, dlo, csq);
                float d1v = fmaf(-2.0f, dhi, csq);
                if (d0v < best[2 * p + 0]) { best[2 * p + 0] = d0v; bidx[2 * p + 0] = gidx; }
                if (d1v < best[2 * p + 1]) { best[2 * p + 1] = d1v; bidx[2 * p + 1] = gidx; }
            }
        }
        __syncthreads();   // protect s_csq before next tile's write
    }

    // Reduce across the 16 tx-lanes (width 16), lower index wins ties.
    #pragma unroll
    for (int i = 0; i < TM; i++) {
        float b = best[i]; int ix = bidx[i];
        #pragma unroll
        for (int o = 8; o; o >>= 1) {
            float ob = __shfl_xor_sync(0xffffffffu, b, o, 16);
            int   oi = __shfl_xor_sync(0xffffffffu, ix, o, 16);
            if (ob < b || (ob == b && oi < ix)) { b = ob; ix = oi; }
        }
        if (tx == 0) s_idx[mrow + i] = ix;
    }
    __syncthreads();

    // Indices as float (0..1023: exactly representable).
    if (tid < BM) idx_out[m0 + tid] = (float)s_idx[tid];

    // Gather z_q rows from codebook (L2-resident), float4.
    const float4* cb4 = reinterpret_cast<const float4*>(cb);
    float4* zq4 = reinterpret_cast<float4*>(zq);
    #pragma unroll 4
    for (int t = tid; t < BM * (D / 4); t += NTHREADS) {
        int m  = t >> 6;        // / (D/4)
        int c4 = t & 63;
        int code = s_idx[m];
        zq4[(size_t)(m0 + m) * (D / 4) + c4] = cb4[(size_t)code * (D / 4) + c4];
    }
}

extern "C" void kernel_launch(void* const* d_in, const int* in_sizes, int n_in,
                              void* d_out, int out_size) {
    const float* z  = (const float*)d_in[0];
    const float* cb = (const float*)d_in[1];
    const int M = in_sizes[0] / D;        // 32768 tokens
    float* out    = (float*)d_out;
    float* zq     = out;                  // [M, D]
    float* idxout = out + (size_t)M * D;  // [M] as float

    csq_kernel<<<(KCODES * 32 + NTHREADS - 1) / NTHREADS, NTHREADS>>>(cb);
    vq_kernel<<<M / BM, NTHREADS>>>(z, cb, zq, idxout);
}

// round 9
// speedup vs baseline: 1.2983x; 1.0430x over previous
#include <cuda_runtime.h>
#include <cstdint>

#define DDIM    256
#define KCODES  1024
#define MTOT    32768
#define BM      128      // tokens per CTA
#define NC      128      // codes per n-chunk
#define KC      32       // dims per k-chunk
#define SROW    36       // smem row stride (floats): 36 mod 32 == 4 -> conflict-free
#define EPSF    2.5f     // > worst-case tf32-truncation distance error (~0.8)

__device__ float g_c_sq[KCODES];
__device__ float g_dist[(size_t)MTOT * KCODES];   // 128MB static scratch

// ---------------- c_sq ----------------
__global__ void csq_kernel(const float* __restrict__ cb) {
    int warp = (blockIdx.x * blockDim.x + threadIdx.x) >> 5;
    int lane = threadIdx.x & 31;
    if (warp >= KCODES) return;
    const float* row = cb + (size_t)warp * DDIM;
    float s = 0.f;
    #pragma unroll
    for (int d = lane; d < DDIM; d += 32) { float v = row[d]; s += v * v; }
    #pragma unroll
    for (int o = 16; o; o >>= 1) s += __shfl_xor_sync(0xffffffffu, s, o);
    if (lane == 0) g_c_sq[warp] = s;
}

__device__ __forceinline__ void mma_tf32(float* c, const uint32_t* a, const uint32_t* b) {
    asm volatile(
        "mma.sync.aligned.m16n8k8.row.col.f32.tf32.tf32.f32 "
        "{%0,%1,%2,%3}, {%4,%5,%6,%7}, {%8,%9}, {%0,%1,%2,%3};"
        : "+f"(c[0]), "+f"(c[1]), "+f"(c[2]), "+f"(c[3])
        : "r"(a[0]), "r"(a[1]), "r"(a[2]), "r"(a[3]), "r"(b[0]), "r"(b[1]));
}

// ---------------- Phase 1: tf32 mma.sync GEMM -> approx distances ----------------
// 8 warps: warp (wm, wn) in 4x2 grid; warp tile m32 x n64.
__global__ __launch_bounds__(256, 2)
void vq_phase1(const float* __restrict__ z, const float* __restrict__ cb) {
    __shared__ float zs[BM * SROW];    // [m][k], k-major, stride 36
    __shared__ float cs[NC * SROW];    // [n][k]
    __shared__ float s_csq[KCODES];

    const int tid = threadIdx.x;
    const int w   = tid >> 5;
    const int l   = tid & 31;
    const int wm  = w & 3;             // 0..3 -> m offset wm*32
    const int wn  = w >> 2;            // 0..1 -> n offset wn*64
    const int m0  = blockIdx.x * BM;
    const int lg  = l >> 2;            // groupID
    const int lt  = l & 3;             // thread-in-group

    #pragma unroll
    for (int i = 0; i < KCODES / 256; i++) s_csq[tid + i * 256] = g_c_sq[tid + i * 256];

    for (int nc0 = 0; nc0 < KCODES; nc0 += NC) {
        float acc[2][8][4];
        #pragma unroll
        for (int it = 0; it < 2; it++)
            #pragma unroll
            for (int j = 0; j < 8; j++)
                #pragma unroll
                for (int q = 0; q < 4; q++) acc[it][j][q] = 0.f;

        for (int k0 = 0; k0 < DDIM; k0 += KC) {
            __syncthreads();   // previous iter's fragment reads done
            // stage z [128 x 32] and cb [128 x 32], k-major, stride-36 rows
            #pragma unroll
            for (int i = 0; i < (BM * KC) / (4 * 256); i++) {
                int lin = tid + i * 256;
                int m = lin >> 3, k4 = (lin & 7) << 2;
                float4 v = *(const float4*)(z + (size_t)(m0 + m) * DDIM + k0 + k4);
                *(float4*)(zs + m * SROW + k4) = v;
            }
            #pragma unroll
            for (int i = 0; i < (NC * KC) / (4 * 256); i++) {
                int lin = tid + i * 256;
                int n = lin >> 3, k4 = (lin & 7) << 2;
                float4 v = *(const float4*)(cb + (size_t)(nc0 + n) * DDIM + k0 + k4);
                *(float4*)(cs + n * SROW + k4) = v;
            }
            __syncthreads();

            #pragma unroll
            for (int ks = 0; ks < KC / 8; ks++) {
                const int kb = ks * 8;
                // A fragments (2 m16 tiles), raw f32 bits as tf32 (HW truncates)
                uint32_t afr[2][4];
                #pragma unroll
                for (int it = 0; it < 2; it++) {
                    const float* ab = zs + (wm * 32 + it * 16) * SROW + kb;
                    afr[it][0] = __float_as_uint(ab[(lg    ) * SROW + lt    ]);
                    afr[it][1] = __float_as_uint(ab[(lg + 8) * SROW + lt    ]);
                    afr[it][2] = __float_as_uint(ab[(lg    ) * SROW + lt + 4]);
                    afr[it][3] = __float_as_uint(ab[(lg + 8) * SROW + lt + 4]);
                }
                // B fragments (8 n8 tiles)
                uint32_t bfr[8][2];
                #pragma unroll
                for (int j = 0; j < 8; j++) {
                    const float* bb = cs + (wn * 64 + j * 8 + lg) * SROW + kb;
                    bfr[j][0] = __float_as_uint(bb[lt    ]);
                    bfr[j][1] = __float_as_uint(bb[lt + 4]);
                }
                #pragma unroll
                for (int it = 0; it < 2; it++)
                    #pragma unroll
                    for (int j = 0; j < 8; j++)
                        mma_tf32(acc[it][j], afr[it], bfr[j]);
            }
        }

        // epilogue: dist = csq - 2*cross, scatter to g_dist
        #pragma unroll
        for (int it = 0; it < 2; it++) {
            const int r0 = wm * 32 + it * 16 + lg;
            #pragma unroll
            for (int j = 0; j < 8; j++) {
                const int c0 = nc0 + wn * 64 + j * 8 + 2 * lt;
                float cq0 = s_csq[c0], cq1 = s_csq[c0 + 1];
                float2 lo, hi;
                lo.x = fmaf(-2.f, acc[it][j][0], cq0);
                lo.y = fmaf(-2.f, acc[it][j][1], cq1);
                hi.x = fmaf(-2.f, acc[it][j][2], cq0);
                hi.y = fmaf(-2.f, acc[it][j][3], cq1);
                *(float2*)(g_dist + (size_t)(m0 + r0    ) * KCODES + c0) = lo;
                *(float2*)(g_dist + (size_t)(m0 + r0 + 8) * KCODES + c0) = hi;
            }
        }
        __syncthreads();
    }
}

// ---------------- Phase 2: exact argmin among EPS-candidates + gather ----------------
__global__ __launch_bounds__(256)
void vq_phase2(const float* __restrict__ z, const float* __restrict__ cb,
               float* __restrict__ zq, float* __restrict__ idx_out) {
    const int m    = (blockIdx.x * blockDim.x + threadIdx.x) >> 5;   // one warp/token
    const int lane = threadIdx.x & 31;

    const float4* d4 = (const float4*)(g_dist + (size_t)m * KCODES);
    float4 vals[8];
    #pragma unroll
    for (int i = 0; i < 8; i++) vals[i] = d4[i * 32 + lane];

    // approx min, lowest index on ties
    float amin = 3.402823466e38f; int aidx = KCODES;
    #pragma unroll
    for (int i = 0; i < 8; i++) {
        int base = (i * 32 + lane) * 4;
        float v[4] = {vals[i].x, vals[i].y, vals[i].z, vals[i].w};
        #pragma unroll
        for (int j = 0; j < 4; j++)
            if (v[j] < amin) { amin = v[j]; aidx = base + j; }
    }
    #pragma unroll
    for (int o = 16; o; o >>= 1) {
        float ob = __shfl_xor_sync(0xffffffffu, amin, o);
        int   oi = __shfl_xor_sync(0xffffffffu, aidx, o);
        if (ob < amin || (ob == amin && oi < aidx)) { amin = ob; aidx = oi; }
    }
    const float thresh = amin + EPSF;

    // exact fp32 rescore of every candidate within EPS of approx min
    float ebest = 3.402823466e38f; int eidx = KCODES;
    const float* zr = z + (size_t)m * DDIM;
    #pragma unroll
    for (int i = 0; i < 8; i++) {
        int base = (i * 32 + lane) * 4;
        float v[4] = {vals[i].x, vals[i].y, vals[i].z, vals[i].w};
        #pragma unroll
        for (int j = 0; j < 4; j++) {
            if (v[j] <= thresh) {
                int code = base + j;
                const float* cr = cb + (size_t)code * DDIM;
                float dot = 0.f;
                #pragma unroll 8
                for (int d = 0; d < DDIM; d++) dot = fmaf(zr[d], cr[d], dot);
                float ed = fmaf(-2.f, dot, g_c_sq[code]);
                if (ed < ebest || (ed == ebest && code < eidx)) { ebest = ed; eidx = code; }
            }
        }
    }
    #pragma unroll
    for (int o = 16; o; o >>= 1) {
        float ob = __shfl_xor_sync(0xffffffffu, ebest, o);
        int   oi = __shfl_xor_sync(0xffffffffu, eidx, o);
        if (ob < ebest || (ob == ebest && oi < eidx)) { ebest = ob; eidx = oi; }
    }

    if (lane == 0) idx_out[m] = (float)eidx;
    const float4* crow = (const float4*)(cb + (size_t)eidx * DDIM);
    float4* zrow = (float4*)(zq + (size_t)m * DDIM);
    zrow[lane]      = crow[lane];
    zrow[lane + 32] = crow[lane + 32];
}

extern "C" void kernel_launch(void* const* d_in, const int* in_sizes, int n_in,
                              void* d_out, int out_size) {
    const float* z  = (const float*)d_in[0];
    const float* cb = (const float*)d_in[1];
    float* out    = (float*)d_out;
    float* zq     = out;                        // [MTOT, DDIM]
    float* idxout = out + (size_t)MTOT * DDIM;  // [MTOT] as float

    csq_kernel<<<(KCODES * 32 + 255) / 256, 256>>>(cb);
    vq_phase1<<<MTOT / BM, 256>>>(z, cb);
    vq_phase2<<<MTOT / 8, 256>>>(z, cb, zq, idxout);
}